// round 13
// baseline (speedup 1.0000x reference)
#include <cuda_runtime.h>
#include <cuda_bf16.h>
#include <math.h>

// ---------------- problem constants ----------------
#define Bv   16
#define Tv   2048
#define DM   160        // d_model
#define DI   320        // d_inner
#define DS   64         // d_state
#define DTR  10         // dt_rank
#define CK   9          // stem conv kernel
#define DC   12         // mamba depthwise conv kernel
#define NB   8
#define BT   (Bv*Tv)    // 32768
#define XD   (DTR + 2*DS) // 138
#define XZW  (2*DI)     // 640

// ---------------- scratch (device globals, allocation-free) ----------------
__device__ float  g_h   [BT*DM];      // residual stream
__device__ float  g_ln  [BT*DM];      // layernorm output
__device__ float  g_xz  [BT*XZW];     // in_proj output (u | z)
__device__ float  g_u   [BT*DI];      // conv+silu output
__device__ float  g_xdbl[BT*XD];      // x_proj output
__device__ float2 g_dd  [Bv*DI*Tv];   // (delta, delta*u) in (b,d,t)
__device__ float2 g_bc  [BT*DS];      // (B_s, C_s) interleaved, (b,t,s)
__device__ float  g_ysc [Bv*DI*Tv];   // scan output in (b,d,t)
__device__ float  g_yg  [BT*DI];      // gated y in (b,t,d)

// ---------------- helpers ----------------
__device__ __forceinline__ float softplusf(float x) {
    return (x > 20.f) ? x : log1pf(expf(x));
}
__device__ __forceinline__ float siluf(float x) {
    return x / (1.f + expf(-x));
}

// ---------------- stem: conv1d (K=9, same pad) + exact GELU ----------------
__global__ void stem_kernel(const float* __restrict__ x,
                            const float* __restrict__ pre_w,
                            const float* __restrict__ pre_b) {
    int t = blockIdx.x, b = blockIdx.y, c = threadIdx.x;
    __shared__ float xs[CK];
    if (c < CK) {
        int tt = t + c - CK/2;
        xs[c] = (tt >= 0 && tt < Tv) ? x[b*Tv + tt] : 0.f;
    }
    __syncthreads();
    float acc = pre_b[c];
#pragma unroll
    for (int k = 0; k < CK; k++) acc = fmaf(pre_w[c*CK + k], xs[k], acc);
    float g = 0.5f * acc * (1.f + erff(acc * 0.7071067811865475f));
    g_h[(b*Tv + t)*DM + c] = g;
}

// ---------------- LayerNorm over DM=160, one warp per row ----------------
__global__ void ln_kernel(const float* __restrict__ gamma,
                          const float* __restrict__ beta) {
    int row  = blockIdx.x * (blockDim.x >> 5) + (threadIdx.x >> 5);
    int lane = threadIdx.x & 31;
    if (row >= BT) return;
    const float* p = g_h + (size_t)row * DM;
    float v[5]; float s = 0.f;
#pragma unroll
    for (int i = 0; i < 5; i++) { v[i] = p[lane + 32*i]; s += v[i]; }
#pragma unroll
    for (int o = 16; o; o >>= 1) s += __shfl_xor_sync(0xffffffffu, s, o);
    float mean = s * (1.f / DM);
    float q = 0.f;
#pragma unroll
    for (int i = 0; i < 5; i++) { float d = v[i] - mean; q += d*d; }
#pragma unroll
    for (int o = 16; o; o >>= 1) q += __shfl_xor_sync(0xffffffffu, q, o);
    float r = rsqrtf(q * (1.f / DM) + 1e-5f);
    float* o = g_ln + (size_t)row * DM;
#pragma unroll
    for (int i = 0; i < 5; i++) {
        int c = lane + 32*i;
        o[c] = (v[i] - mean) * r * gamma[c] + beta[c];
    }
}

// ---------------- SGEMM: C[M,N] = A[M,K] @ W[N,K]^T (+ Res) ----------------
// BM=128 BN=64 BK=16, 256 threads, 8x4 micro-tile. M%128==0, K%16==0.
template <bool RES>
__global__ void __launch_bounds__(256)
sgemm_nt(const float* __restrict__ A, const float* __restrict__ W,
         const float* __restrict__ Res, float* __restrict__ C,
         int M, int N, int K) {
    __shared__ float As[16][128];
    __shared__ float Ws[16][64];
    int tid = threadIdx.x;
    int tx  = tid & 15;   // n dim
    int ty  = tid >> 4;   // m dim
    int m0  = blockIdx.y * 128;
    int n0  = blockIdx.x * 64;
    float acc[8][4];
#pragma unroll
    for (int i = 0; i < 8; i++)
#pragma unroll
        for (int j = 0; j < 4; j++) acc[i][j] = 0.f;

    int lr = tid >> 2;        // 0..63
    int lk = (tid & 3) * 4;   // 0,4,8,12

    for (int k0 = 0; k0 < K; k0 += 16) {
#pragma unroll
        for (int p = 0; p < 2; p++) {
            int m = lr + p*64;
            float4 av = *reinterpret_cast<const float4*>(
                A + (size_t)(m0 + m)*K + k0 + lk);
            As[lk+0][m] = av.x; As[lk+1][m] = av.y;
            As[lk+2][m] = av.z; As[lk+3][m] = av.w;
        }
        {
            float4 wv = make_float4(0.f,0.f,0.f,0.f);
            if (n0 + lr < N)
                wv = *reinterpret_cast<const float4*>(
                    W + (size_t)(n0 + lr)*K + k0 + lk);
            Ws[lk+0][lr] = wv.x; Ws[lk+1][lr] = wv.y;
            Ws[lk+2][lr] = wv.z; Ws[lk+3][lr] = wv.w;
        }
        __syncthreads();
#pragma unroll
        for (int k = 0; k < 16; k++) {
            float a[8], w[4];
#pragma unroll
            for (int i = 0; i < 8; i++) a[i] = As[k][ty*8 + i];
#pragma unroll
            for (int j = 0; j < 4; j++) w[j] = Ws[k][tx*4 + j];
#pragma unroll
            for (int i = 0; i < 8; i++)
#pragma unroll
                for (int j = 0; j < 4; j++)
                    acc[i][j] = fmaf(a[i], w[j], acc[i][j]);
        }
        __syncthreads();
    }
#pragma unroll
    for (int i = 0; i < 8; i++) {
        int m = m0 + ty*8 + i;
#pragma unroll
        for (int j = 0; j < 4; j++) {
            int n = n0 + tx*4 + j;
            if (n < N) {
                float v = acc[i][j];
                if (RES) v += Res[(size_t)m*N + n];
                C[(size_t)m*N + n] = v;
            }
        }
    }
}

// ---------------- depthwise causal conv (K=12) + bias + SiLU ----------------
// reads u = g_xz[..., 0:320], writes g_u. Tile: 64 t x 64 d per block.
__global__ void __launch_bounds__(256)
conv_kernel(const float* __restrict__ cw, const float* __restrict__ cb) {
    __shared__ float uin[64 + DC - 1][64];   // [75][64]
    __shared__ float cwT[DC][64];
    __shared__ float cbs[64];
    int t0 = blockIdx.x * 64;
    int d0 = blockIdx.y * 64;
    int b  = blockIdx.z;
    int tid = threadIdx.x;

    for (int idx = tid; idx < (64 + DC - 1) * 64; idx += 256) {
        int r = idx >> 6, dd = idx & 63;
        int t = t0 - (DC - 1) + r;
        uin[r][dd] = (t >= 0) ? g_xz[((size_t)(b*Tv) + t)*XZW + d0 + dd] : 0.f;
    }
    for (int idx = tid; idx < 64 * DC; idx += 256) {
        int dd = idx / DC, k = idx % DC;
        cwT[k][dd] = cw[(d0 + dd)*DC + k];
    }
    if (tid < 64) cbs[tid] = cb[d0 + tid];
    __syncthreads();

    for (int q = 0; q < 16; q++) {
        int lin = tid + q * 256;
        int tt = lin >> 6, dd = lin & 63;
        float acc = cbs[dd];
#pragma unroll
        for (int k = 0; k < DC; k++) acc = fmaf(uin[tt + k][dd], cwT[k][dd], acc);
        g_u[((size_t)(b*Tv) + t0 + tt)*DI + d0 + dd] = siluf(acc);
    }
}

// ---------------- dt projection + softplus, write (delta, delta*u) ----------
// one block: (b, 32 timesteps). blockDim (32,8).
__global__ void __launch_bounds__(256)
dt_kernel(const float* __restrict__ dtw, const float* __restrict__ dtb) {
    __shared__ float xdt[32][11];        // [t][r] padded
    __shared__ float dtws[DI*DTR];       // 3200 floats
    __shared__ float us[32][33];         // [t][d_local]
    int t0 = blockIdx.x * 32;
    int b  = blockIdx.y;
    int tx = threadIdx.x, ty = threadIdx.y;
    int tid = ty * 32 + tx;

    for (int idx = tid; idx < 32 * DTR; idx += 256)
        xdt[idx / DTR][idx % DTR] = g_xdbl[((size_t)(b*Tv) + t0 + idx/DTR)*XD + idx%DTR];
    for (int idx = tid; idx < DI*DTR; idx += 256) dtws[idx] = dtw[idx];
    __syncthreads();

    for (int dch = 0; dch < DI/32; dch++) {
        for (int p = 0; p < 4; p++) {
            int lin = tid + p * 256;
            int tl = lin >> 5, dl = lin & 31;
            us[tl][dl] = g_u[((size_t)(b*Tv) + t0 + tl)*DI + dch*32 + dl];
        }
        __syncthreads();
#pragma unroll
        for (int jj = 0; jj < 4; jj++) {
            int dl = ty * 4 + jj;
            int d  = dch * 32 + dl;
            float acc = dtb[d];
#pragma unroll
            for (int r = 0; r < DTR; r++)
                acc = fmaf(xdt[tx][r], dtws[d*DTR + r], acc);
            float delta = softplusf(acc);
            float uu = us[tx][dl];
            g_dd[((size_t)(b*DI + d))*Tv + t0 + tx] = make_float2(delta, delta * uu);
        }
        __syncthreads();
    }
}

// ---------------- repack B,C columns of x_dbl into interleaved float2 -------
__global__ void bc_kernel() {
    int s = threadIdx.x;                     // 0..63
    int t = blockIdx.x * blockDim.y + threadIdx.y;
    int b = blockIdx.y;
    size_t row = (size_t)b*Tv + t;
    float Bs = g_xdbl[row*XD + DTR + s];
    float Cs = g_xdbl[row*XD + DTR + DS + s];
    g_bc[row*DS + s] = make_float2(Bs, Cs);
}

// ---------------- selective scan: one warp per (b,d) channel ----------------
__global__ void __launch_bounds__(256)
scan_kernel(const float* __restrict__ A_log) {
    int w    = blockIdx.x * 8 + (threadIdx.x >> 5);
    int lane = threadIdx.x & 31;
    int b = w / DI, d = w % DI;

    // A[s] = -exp(A_log[d][s]); premultiply by log2(e) for exp2f
    float2 al = reinterpret_cast<const float2*>(A_log + (size_t)d*DS)[lane];
    const float L2E = 1.4426950408889634f;
    float a0 = -expf(al.x) * L2E;
    float a1 = -expf(al.y) * L2E;

    const float2* ddp = g_dd + (size_t)(b*DI + d)*Tv;
    const float2* bcp = g_bc + (size_t)b*Tv*DS + 2*lane;
    float*        yo  = g_ysc + (size_t)(b*DI + d)*Tv;

    float h0 = 0.f, h1 = 0.f, ys = 0.f;
    for (int t = 0; t < Tv; t += 32) {
#pragma unroll
        for (int j = 0; j < 32; j++) {
            float2 dv  = ddp[t + j];
            float4 bcv = *reinterpret_cast<const float4*>(bcp + (size_t)(t + j)*DS);
            float dA0 = exp2f(dv.x * a0);
            float dA1 = exp2f(dv.x * a1);
            h0 = fmaf(h0, dA0, dv.y * bcv.x);
            h1 = fmaf(h1, dA1, dv.y * bcv.z);
            float p = fmaf(h0, bcv.y, h1 * bcv.w);
#pragma unroll
            for (int o = 16; o; o >>= 1) p += __shfl_xor_sync(0xffffffffu, p, o);
            if (lane == j) ys = p;
        }
        yo[t + lane] = ys;   // coalesced: 32 consecutive timesteps
    }
}

// ---------------- gate: yg(b,t,d) = (ysc + u*Dskip) * silu(z), transpose -----
__global__ void __launch_bounds__(256)
gate_kernel(const float* __restrict__ Dsk) {
    __shared__ float ts[32][33];
    int t0 = blockIdx.x * 32;
    int d0 = blockIdx.y * 32;
    int b  = blockIdx.z;
    int tx = threadIdx.x, ty = threadIdx.y;

#pragma unroll
    for (int p = 0; p < 4; p++) {
        int r = ty + p * 8;
        ts[r][tx] = g_ysc[((size_t)(b*DI) + d0 + r)*Tv + t0 + tx];  // [d_local][t_local]
    }
    __syncthreads();
#pragma unroll
    for (int p = 0; p < 4; p++) {
        int tt = ty + p * 8;
        int d  = d0 + tx;
        size_t row = (size_t)b*Tv + t0 + tt;
        float y = ts[tx][tt];
        float u = g_u[row*DI + d];
        float z = g_xz[row*XZW + DI + d];
        g_yg[row*DI + d] = (y + u * Dsk[d]) * siluf(z);
    }
}

// ---------------- head: out[b,t] = h . head_w + head_b, warp per row --------
__global__ void head_kernel(const float* __restrict__ hw,
                            const float* __restrict__ hb,
                            float* __restrict__ out) {
    int row  = blockIdx.x * (blockDim.x >> 5) + (threadIdx.x >> 5);
    int lane = threadIdx.x & 31;
    if (row >= BT) return;
    const float* p = g_h + (size_t)row * DM;
    float s = 0.f;
#pragma unroll
    for (int i = 0; i < 5; i++) {
        int c = lane + 32*i;
        s = fmaf(p[c], hw[c], s);
    }
#pragma unroll
    for (int o = 16; o; o >>= 1) s += __shfl_xor_sync(0xffffffffu, s, o);
    if (lane == 0) out[row] = s + hb[0];
}

// ---------------- orchestration ----------------
extern "C" void kernel_launch(void* const* d_in, const int* in_sizes, int n_in,
                              void* d_out, int out_size) {
    const float* x       = (const float*)d_in[0];
    const float* pre_w   = (const float*)d_in[1];
    const float* pre_b   = (const float*)d_in[2];
    const float* ln_g    = (const float*)d_in[3];
    const float* ln_b    = (const float*)d_in[4];
    const float* in_w    = (const float*)d_in[5];
    const float* conv_w  = (const float*)d_in[6];
    const float* conv_b  = (const float*)d_in[7];
    const float* xproj_w = (const float*)d_in[8];
    const float* dt_w    = (const float*)d_in[9];
    const float* dt_b    = (const float*)d_in[10];
    const float* A_log   = (const float*)d_in[11];
    const float* D_skip  = (const float*)d_in[12];
    const float* out_w   = (const float*)d_in[13];
    const float* head_w  = (const float*)d_in[14];
    const float* head_b  = (const float*)d_in[15];
    float* out = (float*)d_out;

    float *p_h, *p_ln, *p_xz, *p_u, *p_xdbl, *p_yg;
    cudaGetSymbolAddress((void**)&p_h,    g_h);
    cudaGetSymbolAddress((void**)&p_ln,   g_ln);
    cudaGetSymbolAddress((void**)&p_xz,   g_xz);
    cudaGetSymbolAddress((void**)&p_u,    g_u);
    cudaGetSymbolAddress((void**)&p_xdbl, g_xdbl);
    cudaGetSymbolAddress((void**)&p_yg,   g_yg);

    // stem
    stem_kernel<<<dim3(Tv, Bv), DM>>>(x, pre_w, pre_b);

    for (int i = 0; i < NB; i++) {
        // layernorm
        ln_kernel<<<BT/8, 256>>>(ln_g + i*DM, ln_b + i*DM);
        // in_proj: (BT,160) @ (640,160)^T -> g_xz
        sgemm_nt<false><<<dim3((XZW + 63)/64, BT/128), 256>>>(
            p_ln, in_w + (size_t)i*XZW*DM, nullptr, p_xz, BT, XZW, DM);
        // depthwise conv + silu
        conv_kernel<<<dim3(Tv/64, DI/64, Bv), 256>>>(
            conv_w + (size_t)i*DI*DC, conv_b + (size_t)i*DI);
        // x_proj: (BT,320) @ (138,320)^T -> g_xdbl
        sgemm_nt<false><<<dim3((XD + 63)/64, BT/128), 256>>>(
            p_u, xproj_w + (size_t)i*XD*DI, nullptr, p_xdbl, BT, XD, DI);
        // dt projection + softplus -> g_dd (b,d,t)
        dt_kernel<<<dim3(Tv/32, Bv), dim3(32, 8)>>>(
            dt_w + (size_t)i*DI*DTR, dt_b + (size_t)i*DI);
        // repack B,C
        bc_kernel<<<dim3(Tv/4, Bv), dim3(64, 4)>>>();
        // selective scan
        scan_kernel<<<(Bv*DI)/8, 256>>>(A_log + (size_t)i*DI*DS);
        // gate + transpose -> g_yg (b,t,d)
        gate_kernel<<<dim3(Tv/32, DI/32, Bv), dim3(32, 8)>>>(D_skip + (size_t)i*DI);
        // out_proj + residual: g_h += g_yg @ out_w^T
        sgemm_nt<true><<<dim3((DM + 63)/64, BT/128), 256>>>(
            p_yg, out_w + (size_t)i*DM*DI, p_h, p_h, BT, DM, DI);
    }

    // head
    head_kernel<<<BT/8, 256>>>(head_w, head_b, out);
}

// round 14
// speedup vs baseline: 1.0012x; 1.0012x over previous
#include <cuda_runtime.h>
#include <cuda_bf16.h>
#include <math.h>

// ---------------- problem constants ----------------
#define Bv   16
#define Tv   2048
#define DM   160        // d_model
#define DI   320        // d_inner
#define DS   64         // d_state
#define DTR  10         // dt_rank
#define CK   9          // stem conv kernel
#define DC   12         // mamba depthwise conv kernel
#define NB   8
#define BT   (Bv*Tv)    // 32768
#define XD   (DTR + 2*DS) // 138
#define XZW  (2*DI)     // 640

// ---------------- scratch (device globals, allocation-free) ----------------
__device__ float  g_h   [BT*DM];      // residual stream
__device__ float  g_ln  [BT*DM];      // layernorm output
__device__ float  g_xz  [BT*XZW];     // in_proj output (u | z)
__device__ float  g_u   [BT*DI];      // conv+silu output
__device__ float  g_xdbl[BT*XD];      // x_proj output
__device__ float2 g_dd  [Bv*DI*Tv];   // (delta, delta*u) in (b,d,t)
__device__ float2 g_bc  [BT*DS];      // (B_s, C_s) interleaved, (b,t,s)
__device__ float  g_ysc [Bv*DI*Tv];   // scan output in (b,d,t)
__device__ float  g_yg  [BT*DI];      // gated y in (b,t,d)

// ---------------- helpers ----------------
__device__ __forceinline__ float softplusf(float x) {
    return (x > 20.f) ? x : log1pf(expf(x));
}
__device__ __forceinline__ float siluf(float x) {
    return x / (1.f + expf(-x));
}

// ---------------- stem: conv1d (K=9, same pad) + exact GELU ----------------
__global__ void stem_kernel(const float* __restrict__ x,
                            const float* __restrict__ pre_w,
                            const float* __restrict__ pre_b) {
    int t = blockIdx.x, b = blockIdx.y, c = threadIdx.x;
    __shared__ float xs[CK];
    if (c < CK) {
        int tt = t + c - CK/2;
        xs[c] = (tt >= 0 && tt < Tv) ? x[b*Tv + tt] : 0.f;
    }
    __syncthreads();
    float acc = pre_b[c];
#pragma unroll
    for (int k = 0; k < CK; k++) acc = fmaf(pre_w[c*CK + k], xs[k], acc);
    float g = 0.5f * acc * (1.f + erff(acc * 0.7071067811865475f));
    g_h[(b*Tv + t)*DM + c] = g;
}

// ---------------- LayerNorm over DM=160, one warp per row ----------------
__global__ void ln_kernel(const float* __restrict__ gamma,
                          const float* __restrict__ beta) {
    int row  = blockIdx.x * (blockDim.x >> 5) + (threadIdx.x >> 5);
    int lane = threadIdx.x & 31;
    if (row >= BT) return;
    const float* p = g_h + (size_t)row * DM;
    float v[5]; float s = 0.f;
#pragma unroll
    for (int i = 0; i < 5; i++) { v[i] = p[lane + 32*i]; s += v[i]; }
#pragma unroll
    for (int o = 16; o; o >>= 1) s += __shfl_xor_sync(0xffffffffu, s, o);
    float mean = s * (1.f / DM);
    float q = 0.f;
#pragma unroll
    for (int i = 0; i < 5; i++) { float d = v[i] - mean; q += d*d; }
#pragma unroll
    for (int o = 16; o; o >>= 1) q += __shfl_xor_sync(0xffffffffu, q, o);
    float r = rsqrtf(q * (1.f / DM) + 1e-5f);
    float* o = g_ln + (size_t)row * DM;
#pragma unroll
    for (int i = 0; i < 5; i++) {
        int c = lane + 32*i;
        o[c] = (v[i] - mean) * r * gamma[c] + beta[c];
    }
}

// ---------------- SGEMM: C[M,N] = A[M,K] @ W[N,K]^T (+ Res) ----------------
// BM=128 BN=64 BK=16, 256 threads, 8x4 micro-tile. M%128==0, K%16==0.
template <bool RES>
__global__ void __launch_bounds__(256)
sgemm_nt(const float* __restrict__ A, const float* __restrict__ W,
         const float* __restrict__ Res, float* __restrict__ C,
         int M, int N, int K) {
    __shared__ float As[16][128];
    __shared__ float Ws[16][64];
    int tid = threadIdx.x;
    int tx  = tid & 15;   // n dim
    int ty  = tid >> 4;   // m dim
    int m0  = blockIdx.y * 128;
    int n0  = blockIdx.x * 64;
    float acc[8][4];
#pragma unroll
    for (int i = 0; i < 8; i++)
#pragma unroll
        for (int j = 0; j < 4; j++) acc[i][j] = 0.f;

    int lr = tid >> 2;        // 0..63
    int lk = (tid & 3) * 4;   // 0,4,8,12

    for (int k0 = 0; k0 < K; k0 += 16) {
#pragma unroll
        for (int p = 0; p < 2; p++) {
            int m = lr + p*64;
            float4 av = *reinterpret_cast<const float4*>(
                A + (size_t)(m0 + m)*K + k0 + lk);
            As[lk+0][m] = av.x; As[lk+1][m] = av.y;
            As[lk+2][m] = av.z; As[lk+3][m] = av.w;
        }
        {
            float4 wv = make_float4(0.f,0.f,0.f,0.f);
            if (n0 + lr < N)
                wv = *reinterpret_cast<const float4*>(
                    W + (size_t)(n0 + lr)*K + k0 + lk);
            Ws[lk+0][lr] = wv.x; Ws[lk+1][lr] = wv.y;
            Ws[lk+2][lr] = wv.z; Ws[lk+3][lr] = wv.w;
        }
        __syncthreads();
#pragma unroll
        for (int k = 0; k < 16; k++) {
            float a[8], w[4];
#pragma unroll
            for (int i = 0; i < 8; i++) a[i] = As[k][ty*8 + i];
#pragma unroll
            for (int j = 0; j < 4; j++) w[j] = Ws[k][tx*4 + j];
#pragma unroll
            for (int i = 0; i < 8; i++)
#pragma unroll
                for (int j = 0; j < 4; j++)
                    acc[i][j] = fmaf(a[i], w[j], acc[i][j]);
        }
        __syncthreads();
    }
#pragma unroll
    for (int i = 0; i < 8; i++) {
        int m = m0 + ty*8 + i;
#pragma unroll
        for (int j = 0; j < 4; j++) {
            int n = n0 + tx*4 + j;
            if (n < N) {
                float v = acc[i][j];
                if (RES) v += Res[(size_t)m*N + n];
                C[(size_t)m*N + n] = v;
            }
        }
    }
}

// ---------------- depthwise causal conv (K=12) + bias + SiLU ----------------
// reads u = g_xz[..., 0:320], writes g_u. Tile: 64 t x 64 d per block.
__global__ void __launch_bounds__(256)
conv_kernel(const float* __restrict__ cw, const float* __restrict__ cb) {
    __shared__ float uin[64 + DC - 1][64];   // [75][64]
    __shared__ float cwT[DC][64];
    __shared__ float cbs[64];
    int t0 = blockIdx.x * 64;
    int d0 = blockIdx.y * 64;
    int b  = blockIdx.z;
    int tid = threadIdx.x;

    for (int idx = tid; idx < (64 + DC - 1) * 64; idx += 256) {
        int r = idx >> 6, dd = idx & 63;
        int t = t0 - (DC - 1) + r;
        uin[r][dd] = (t >= 0) ? g_xz[((size_t)(b*Tv) + t)*XZW + d0 + dd] : 0.f;
    }
    for (int idx = tid; idx < 64 * DC; idx += 256) {
        int dd = idx / DC, k = idx % DC;
        cwT[k][dd] = cw[(d0 + dd)*DC + k];
    }
    if (tid < 64) cbs[tid] = cb[d0 + tid];
    __syncthreads();

    for (int q = 0; q < 16; q++) {
        int lin = tid + q * 256;
        int tt = lin >> 6, dd = lin & 63;
        float acc = cbs[dd];
#pragma unroll
        for (int k = 0; k < DC; k++) acc = fmaf(uin[tt + k][dd], cwT[k][dd], acc);
        g_u[((size_t)(b*Tv) + t0 + tt)*DI + d0 + dd] = siluf(acc);
    }
}

// ---------------- dt projection + softplus, write (delta, delta*u) ----------
// one block: (b, 32 timesteps). blockDim (32,8).
__global__ void __launch_bounds__(256)
dt_kernel(const float* __restrict__ dtw, const float* __restrict__ dtb) {
    __shared__ float xdt[32][11];        // [t][r] padded
    __shared__ float dtws[DI*DTR];       // 3200 floats
    __shared__ float us[32][33];         // [t][d_local]
    int t0 = blockIdx.x * 32;
    int b  = blockIdx.y;
    int tx = threadIdx.x, ty = threadIdx.y;
    int tid = ty * 32 + tx;

    for (int idx = tid; idx < 32 * DTR; idx += 256)
        xdt[idx / DTR][idx % DTR] = g_xdbl[((size_t)(b*Tv) + t0 + idx/DTR)*XD + idx%DTR];
    for (int idx = tid; idx < DI*DTR; idx += 256) dtws[idx] = dtw[idx];
    __syncthreads();

    for (int dch = 0; dch < DI/32; dch++) {
        for (int p = 0; p < 4; p++) {
            int lin = tid + p * 256;
            int tl = lin >> 5, dl = lin & 31;
            us[tl][dl] = g_u[((size_t)(b*Tv) + t0 + tl)*DI + dch*32 + dl];
        }
        __syncthreads();
#pragma unroll
        for (int jj = 0; jj < 4; jj++) {
            int dl = ty * 4 + jj;
            int d  = dch * 32 + dl;
            float acc = dtb[d];
#pragma unroll
            for (int r = 0; r < DTR; r++)
                acc = fmaf(xdt[tx][r], dtws[d*DTR + r], acc);
            float delta = softplusf(acc);
            float uu = us[tx][dl];
            g_dd[((size_t)(b*DI + d))*Tv + t0 + tx] = make_float2(delta, delta * uu);
        }
        __syncthreads();
    }
}

// ---------------- repack B,C columns of x_dbl into interleaved float2 -------
__global__ void bc_kernel() {
    int s = threadIdx.x;                     // 0..63
    int t = blockIdx.x * blockDim.y + threadIdx.y;
    int b = blockIdx.y;
    size_t row = (size_t)b*Tv + t;
    float Bs = g_xdbl[row*XD + DTR + s];
    float Cs = g_xdbl[row*XD + DTR + DS + s];
    g_bc[row*DS + s] = make_float2(Bs, Cs);
}

// ---------------- selective scan: one warp per (b,d) channel ----------------
__global__ void __launch_bounds__(256)
scan_kernel(const float* __restrict__ A_log) {
    int w    = blockIdx.x * 8 + (threadIdx.x >> 5);
    int lane = threadIdx.x & 31;
    int b = w / DI, d = w % DI;

    // A[s] = -exp(A_log[d][s]); premultiply by log2(e) for exp2f
    float2 al = reinterpret_cast<const float2*>(A_log + (size_t)d*DS)[lane];
    const float L2E = 1.4426950408889634f;
    float a0 = -expf(al.x) * L2E;
    float a1 = -expf(al.y) * L2E;

    const float2* ddp = g_dd + (size_t)(b*DI + d)*Tv;
    const float2* bcp = g_bc + (size_t)b*Tv*DS + 2*lane;
    float*        yo  = g_ysc + (size_t)(b*DI + d)*Tv;

    float h0 = 0.f, h1 = 0.f, ys = 0.f;
    for (int t = 0; t < Tv; t += 32) {
#pragma unroll
        for (int j = 0; j < 32; j++) {
            float2 dv  = ddp[t + j];
            float4 bcv = *reinterpret_cast<const float4*>(bcp + (size_t)(t + j)*DS);
            float dA0 = exp2f(dv.x * a0);
            float dA1 = exp2f(dv.x * a1);
            h0 = fmaf(h0, dA0, dv.y * bcv.x);
            h1 = fmaf(h1, dA1, dv.y * bcv.z);
            float p = fmaf(h0, bcv.y, h1 * bcv.w);
#pragma unroll
            for (int o = 16; o; o >>= 1) p += __shfl_xor_sync(0xffffffffu, p, o);
            if (lane == j) ys = p;
        }
        yo[t + lane] = ys;   // coalesced: 32 consecutive timesteps
    }
}

// ---------------- gate: yg(b,t,d) = (ysc + u*Dskip) * silu(z), transpose -----
__global__ void __launch_bounds__(256)
gate_kernel(const float* __restrict__ Dsk) {
    __shared__ float ts[32][33];
    int t0 = blockIdx.x * 32;
    int d0 = blockIdx.y * 32;
    int b  = blockIdx.z;
    int tx = threadIdx.x, ty = threadIdx.y;

#pragma unroll
    for (int p = 0; p < 4; p++) {
        int r = ty + p * 8;
        ts[r][tx] = g_ysc[((size_t)(b*DI) + d0 + r)*Tv + t0 + tx];  // [d_local][t_local]
    }
    __syncthreads();
#pragma unroll
    for (int p = 0; p < 4; p++) {
        int tt = ty + p * 8;
        int d  = d0 + tx;
        size_t row = (size_t)b*Tv + t0 + tt;
        float y = ts[tx][tt];
        float u = g_u[row*DI + d];
        float z = g_xz[row*XZW + DI + d];
        g_yg[row*DI + d] = (y + u * Dsk[d]) * siluf(z);
    }
}

// ---------------- head: out[b,t] = h . head_w + head_b, warp per row --------
__global__ void head_kernel(const float* __restrict__ hw,
                            const float* __restrict__ hb,
                            float* __restrict__ out) {
    int row  = blockIdx.x * (blockDim.x >> 5) + (threadIdx.x >> 5);
    int lane = threadIdx.x & 31;
    if (row >= BT) return;
    const float* p = g_h + (size_t)row * DM;
    float s = 0.f;
#pragma unroll
    for (int i = 0; i < 5; i++) {
        int c = lane + 32*i;
        s = fmaf(p[c], hw[c], s);
    }
#pragma unroll
    for (int o = 16; o; o >>= 1) s += __shfl_xor_sync(0xffffffffu, s, o);
    if (lane == 0) out[row] = s + hb[0];
}

// ---------------- orchestration ----------------
extern "C" void kernel_launch(void* const* d_in, const int* in_sizes, int n_in,
                              void* d_out, int out_size) {
    const float* x       = (const float*)d_in[0];
    const float* pre_w   = (const float*)d_in[1];
    const float* pre_b   = (const float*)d_in[2];
    const float* ln_g    = (const float*)d_in[3];
    const float* ln_b    = (const float*)d_in[4];
    const float* in_w    = (const float*)d_in[5];
    const float* conv_w  = (const float*)d_in[6];
    const float* conv_b  = (const float*)d_in[7];
    const float* xproj_w = (const float*)d_in[8];
    const float* dt_w    = (const float*)d_in[9];
    const float* dt_b    = (const float*)d_in[10];
    const float* A_log   = (const float*)d_in[11];
    const float* D_skip  = (const float*)d_in[12];
    const float* out_w   = (const float*)d_in[13];
    const float* head_w  = (const float*)d_in[14];
    const float* head_b  = (const float*)d_in[15];
    float* out = (float*)d_out;

    float *p_h, *p_ln, *p_xz, *p_u, *p_xdbl, *p_yg;
    cudaGetSymbolAddress((void**)&p_h,    g_h);
    cudaGetSymbolAddress((void**)&p_ln,   g_ln);
    cudaGetSymbolAddress((void**)&p_xz,   g_xz);
    cudaGetSymbolAddress((void**)&p_u,    g_u);
    cudaGetSymbolAddress((void**)&p_xdbl, g_xdbl);
    cudaGetSymbolAddress((void**)&p_yg,   g_yg);

    // stem
    stem_kernel<<<dim3(Tv, Bv), DM>>>(x, pre_w, pre_b);

    for (int i = 0; i < NB; i++) {
        // layernorm
        ln_kernel<<<BT/8, 256>>>(ln_g + i*DM, ln_b + i*DM);
        // in_proj: (BT,160) @ (640,160)^T -> g_xz
        sgemm_nt<false><<<dim3((XZW + 63)/64, BT/128), 256>>>(
            p_ln, in_w + (size_t)i*XZW*DM, nullptr, p_xz, BT, XZW, DM);
        // depthwise conv + silu
        conv_kernel<<<dim3(Tv/64, DI/64, Bv), 256>>>(
            conv_w + (size_t)i*DI*DC, conv_b + (size_t)i*DI);
        // x_proj: (BT,320) @ (138,320)^T -> g_xdbl
        sgemm_nt<false><<<dim3((XD + 63)/64, BT/128), 256>>>(
            p_u, xproj_w + (size_t)i*XD*DI, nullptr, p_xdbl, BT, XD, DI);
        // dt projection + softplus -> g_dd (b,d,t)
        dt_kernel<<<dim3(Tv/32, Bv), dim3(32, 8)>>>(
            dt_w + (size_t)i*DI*DTR, dt_b + (size_t)i*DI);
        // repack B,C
        bc_kernel<<<dim3(Tv/4, Bv), dim3(64, 4)>>>();
        // selective scan
        scan_kernel<<<(Bv*DI)/8, 256>>>(A_log + (size_t)i*DI*DS);
        // gate + transpose -> g_yg (b,t,d)
        gate_kernel<<<dim3(Tv/32, DI/32, Bv), dim3(32, 8)>>>(D_skip + (size_t)i*DI);
        // out_proj + residual: g_h += g_yg @ out_w^T
        sgemm_nt<true><<<dim3((DM + 63)/64, BT/128), 256>>>(
            p_yg, out_w + (size_t)i*DM*DI, p_h, p_h, BT, DM, DI);
    }

    // head
    head_kernel<<<BT/8, 256>>>(head_w, head_b, out);
}

// round 15
// speedup vs baseline: 1.0019x; 1.0007x over previous
#include <cuda_runtime.h>
#include <cuda_bf16.h>
#include <math.h>

// ---------------- problem constants ----------------
#define Bv   16
#define Tv   2048
#define DM   160        // d_model
#define DI   320        // d_inner
#define DS   64         // d_state
#define DTR  10         // dt_rank
#define CK   9          // stem conv kernel
#define DC   12         // mamba depthwise conv kernel
#define NB   8
#define BT   (Bv*Tv)    // 32768
#define XD   (DTR + 2*DS) // 138
#define XZW  (2*DI)     // 640

// ---------------- scratch (device globals, allocation-free) ----------------
__device__ float  g_h   [BT*DM];      // residual stream
__device__ float  g_ln  [BT*DM];      // layernorm output
__device__ float  g_xz  [BT*XZW];     // in_proj output (u | z)
__device__ float  g_u   [BT*DI];      // conv+silu output
__device__ float  g_xdbl[BT*XD];      // x_proj output
__device__ float2 g_dd  [Bv*DI*Tv];   // (delta, delta*u) in (b,d,t)
__device__ float2 g_bc  [BT*DS];      // (B_s, C_s) interleaved, (b,t,s)
__device__ float  g_ysc [Bv*DI*Tv];   // scan output in (b,d,t)
__device__ float  g_yg  [BT*DI];      // gated y in (b,t,d)

// ---------------- helpers ----------------
__device__ __forceinline__ float softplusf(float x) {
    return (x > 20.f) ? x : log1pf(expf(x));
}
__device__ __forceinline__ float siluf(float x) {
    return x / (1.f + expf(-x));
}

// ---------------- stem: conv1d (K=9, same pad) + exact GELU ----------------
__global__ void stem_kernel(const float* __restrict__ x,
                            const float* __restrict__ pre_w,
                            const float* __restrict__ pre_b) {
    int t = blockIdx.x, b = blockIdx.y, c = threadIdx.x;
    __shared__ float xs[CK];
    if (c < CK) {
        int tt = t + c - CK/2;
        xs[c] = (tt >= 0 && tt < Tv) ? x[b*Tv + tt] : 0.f;
    }
    __syncthreads();
    float acc = pre_b[c];
#pragma unroll
    for (int k = 0; k < CK; k++) acc = fmaf(pre_w[c*CK + k], xs[k], acc);
    float g = 0.5f * acc * (1.f + erff(acc * 0.7071067811865475f));
    g_h[(b*Tv + t)*DM + c] = g;
}

// ---------------- LayerNorm over DM=160, one warp per row ----------------
__global__ void ln_kernel(const float* __restrict__ gamma,
                          const float* __restrict__ beta) {
    int row  = blockIdx.x * (blockDim.x >> 5) + (threadIdx.x >> 5);
    int lane = threadIdx.x & 31;
    if (row >= BT) return;
    const float* p = g_h + (size_t)row * DM;
    float v[5]; float s = 0.f;
#pragma unroll
    for (int i = 0; i < 5; i++) { v[i] = p[lane + 32*i]; s += v[i]; }
#pragma unroll
    for (int o = 16; o; o >>= 1) s += __shfl_xor_sync(0xffffffffu, s, o);
    float mean = s * (1.f / DM);
    float q = 0.f;
#pragma unroll
    for (int i = 0; i < 5; i++) { float d = v[i] - mean; q += d*d; }
#pragma unroll
    for (int o = 16; o; o >>= 1) q += __shfl_xor_sync(0xffffffffu, q, o);
    float r = rsqrtf(q * (1.f / DM) + 1e-5f);
    float* o = g_ln + (size_t)row * DM;
#pragma unroll
    for (int i = 0; i < 5; i++) {
        int c = lane + 32*i;
        o[c] = (v[i] - mean) * r * gamma[c] + beta[c];
    }
}

// ---------------- SGEMM: C[M,N] = A[M,K] @ W[N,K]^T (+ Res) ----------------
// BM=128 BN=64 BK=16, 256 threads, 8x4 micro-tile. M%128==0, K%16==0.
template <bool RES>
__global__ void __launch_bounds__(256)
sgemm_nt(const float* __restrict__ A, const float* __restrict__ W,
         const float* __restrict__ Res, float* __restrict__ C,
         int M, int N, int K) {
    __shared__ float As[16][128];
    __shared__ float Ws[16][64];
    int tid = threadIdx.x;
    int tx  = tid & 15;   // n dim
    int ty  = tid >> 4;   // m dim
    int m0  = blockIdx.y * 128;
    int n0  = blockIdx.x * 64;
    float acc[8][4];
#pragma unroll
    for (int i = 0; i < 8; i++)
#pragma unroll
        for (int j = 0; j < 4; j++) acc[i][j] = 0.f;

    int lr = tid >> 2;        // 0..63
    int lk = (tid & 3) * 4;   // 0,4,8,12

    for (int k0 = 0; k0 < K; k0 += 16) {
#pragma unroll
        for (int p = 0; p < 2; p++) {
            int m = lr + p*64;
            float4 av = *reinterpret_cast<const float4*>(
                A + (size_t)(m0 + m)*K + k0 + lk);
            As[lk+0][m] = av.x; As[lk+1][m] = av.y;
            As[lk+2][m] = av.z; As[lk+3][m] = av.w;
        }
        {
            float4 wv = make_float4(0.f,0.f,0.f,0.f);
            if (n0 + lr < N)
                wv = *reinterpret_cast<const float4*>(
                    W + (size_t)(n0 + lr)*K + k0 + lk);
            Ws[lk+0][lr] = wv.x; Ws[lk+1][lr] = wv.y;
            Ws[lk+2][lr] = wv.z; Ws[lk+3][lr] = wv.w;
        }
        __syncthreads();
#pragma unroll
        for (int k = 0; k < 16; k++) {
            float a[8], w[4];
#pragma unroll
            for (int i = 0; i < 8; i++) a[i] = As[k][ty*8 + i];
#pragma unroll
            for (int j = 0; j < 4; j++) w[j] = Ws[k][tx*4 + j];
#pragma unroll
            for (int i = 0; i < 8; i++)
#pragma unroll
                for (int j = 0; j < 4; j++)
                    acc[i][j] = fmaf(a[i], w[j], acc[i][j]);
        }
        __syncthreads();
    }
#pragma unroll
    for (int i = 0; i < 8; i++) {
        int m = m0 + ty*8 + i;
#pragma unroll
        for (int j = 0; j < 4; j++) {
            int n = n0 + tx*4 + j;
            if (n < N) {
                float v = acc[i][j];
                if (RES) v += Res[(size_t)m*N + n];
                C[(size_t)m*N + n] = v;
            }
        }
    }
}

// ---------------- depthwise causal conv (K=12) + bias + SiLU ----------------
// reads u = g_xz[..., 0:320], writes g_u. Tile: 64 t x 64 d per block.
__global__ void __launch_bounds__(256)
conv_kernel(const float* __restrict__ cw, const float* __restrict__ cb) {
    __shared__ float uin[64 + DC - 1][64];   // [75][64]
    __shared__ float cwT[DC][64];
    __shared__ float cbs[64];
    int t0 = blockIdx.x * 64;
    int d0 = blockIdx.y * 64;
    int b  = blockIdx.z;
    int tid = threadIdx.x;

    for (int idx = tid; idx < (64 + DC - 1) * 64; idx += 256) {
        int r = idx >> 6, dd = idx & 63;
        int t = t0 - (DC - 1) + r;
        uin[r][dd] = (t >= 0) ? g_xz[((size_t)(b*Tv) + t)*XZW + d0 + dd] : 0.f;
    }
    for (int idx = tid; idx < 64 * DC; idx += 256) {
        int dd = idx / DC, k = idx % DC;
        cwT[k][dd] = cw[(d0 + dd)*DC + k];
    }
    if (tid < 64) cbs[tid] = cb[d0 + tid];
    __syncthreads();

    for (int q = 0; q < 16; q++) {
        int lin = tid + q * 256;
        int tt = lin >> 6, dd = lin & 63;
        float acc = cbs[dd];
#pragma unroll
        for (int k = 0; k < DC; k++) acc = fmaf(uin[tt + k][dd], cwT[k][dd], acc);
        g_u[((size_t)(b*Tv) + t0 + tt)*DI + d0 + dd] = siluf(acc);
    }
}

// ---------------- dt projection + softplus, write (delta, delta*u) ----------
// one block: (b, 32 timesteps). blockDim (32,8).
__global__ void __launch_bounds__(256)
dt_kernel(const float* __restrict__ dtw, const float* __restrict__ dtb) {
    __shared__ float xdt[32][11];        // [t][r] padded
    __shared__ float dtws[DI*DTR];       // 3200 floats
    __shared__ float us[32][33];         // [t][d_local]
    int t0 = blockIdx.x * 32;
    int b  = blockIdx.y;
    int tx = threadIdx.x, ty = threadIdx.y;
    int tid = ty * 32 + tx;

    for (int idx = tid; idx < 32 * DTR; idx += 256)
        xdt[idx / DTR][idx % DTR] = g_xdbl[((size_t)(b*Tv) + t0 + idx/DTR)*XD + idx%DTR];
    for (int idx = tid; idx < DI*DTR; idx += 256) dtws[idx] = dtw[idx];
    __syncthreads();

    for (int dch = 0; dch < DI/32; dch++) {
        for (int p = 0; p < 4; p++) {
            int lin = tid + p * 256;
            int tl = lin >> 5, dl = lin & 31;
            us[tl][dl] = g_u[((size_t)(b*Tv) + t0 + tl)*DI + dch*32 + dl];
        }
        __syncthreads();
#pragma unroll
        for (int jj = 0; jj < 4; jj++) {
            int dl = ty * 4 + jj;
            int d  = dch * 32 + dl;
            float acc = dtb[d];
#pragma unroll
            for (int r = 0; r < DTR; r++)
                acc = fmaf(xdt[tx][r], dtws[d*DTR + r], acc);
            float delta = softplusf(acc);
            float uu = us[tx][dl];
            g_dd[((size_t)(b*DI + d))*Tv + t0 + tx] = make_float2(delta, delta * uu);
        }
        __syncthreads();
    }
}

// ---------------- repack B,C columns of x_dbl into interleaved float2 -------
__global__ void bc_kernel() {
    int s = threadIdx.x;                     // 0..63
    int t = blockIdx.x * blockDim.y + threadIdx.y;
    int b = blockIdx.y;
    size_t row = (size_t)b*Tv + t;
    float Bs = g_xdbl[row*XD + DTR + s];
    float Cs = g_xdbl[row*XD + DTR + DS + s];
    g_bc[row*DS + s] = make_float2(Bs, Cs);
}

// ---------------- selective scan: one warp per (b,d) channel ----------------
__global__ void __launch_bounds__(256)
scan_kernel(const float* __restrict__ A_log) {
    int w    = blockIdx.x * 8 + (threadIdx.x >> 5);
    int lane = threadIdx.x & 31;
    int b = w / DI, d = w % DI;

    // A[s] = -exp(A_log[d][s]); premultiply by log2(e) for exp2f
    float2 al = reinterpret_cast<const float2*>(A_log + (size_t)d*DS)[lane];
    const float L2E = 1.4426950408889634f;
    float a0 = -expf(al.x) * L2E;
    float a1 = -expf(al.y) * L2E;

    const float2* ddp = g_dd + (size_t)(b*DI + d)*Tv;
    const float2* bcp = g_bc + (size_t)b*Tv*DS + 2*lane;
    float*        yo  = g_ysc + (size_t)(b*DI + d)*Tv;

    float h0 = 0.f, h1 = 0.f, ys = 0.f;
    for (int t = 0; t < Tv; t += 32) {
#pragma unroll
        for (int j = 0; j < 32; j++) {
            float2 dv  = ddp[t + j];
            float4 bcv = *reinterpret_cast<const float4*>(bcp + (size_t)(t + j)*DS);
            float dA0 = exp2f(dv.x * a0);
            float dA1 = exp2f(dv.x * a1);
            h0 = fmaf(h0, dA0, dv.y * bcv.x);
            h1 = fmaf(h1, dA1, dv.y * bcv.z);
            float p = fmaf(h0, bcv.y, h1 * bcv.w);
#pragma unroll
            for (int o = 16; o; o >>= 1) p += __shfl_xor_sync(0xffffffffu, p, o);
            if (lane == j) ys = p;
        }
        yo[t + lane] = ys;   // coalesced: 32 consecutive timesteps
    }
}

// ---------------- gate: yg(b,t,d) = (ysc + u*Dskip) * silu(z), transpose -----
__global__ void __launch_bounds__(256)
gate_kernel(const float* __restrict__ Dsk) {
    __shared__ float ts[32][33];
    int t0 = blockIdx.x * 32;
    int d0 = blockIdx.y * 32;
    int b  = blockIdx.z;
    int tx = threadIdx.x, ty = threadIdx.y;

#pragma unroll
    for (int p = 0; p < 4; p++) {
        int r = ty + p * 8;
        ts[r][tx] = g_ysc[((size_t)(b*DI) + d0 + r)*Tv + t0 + tx];  // [d_local][t_local]
    }
    __syncthreads();
#pragma unroll
    for (int p = 0; p < 4; p++) {
        int tt = ty + p * 8;
        int d  = d0 + tx;
        size_t row = (size_t)b*Tv + t0 + tt;
        float y = ts[tx][tt];
        float u = g_u[row*DI + d];
        float z = g_xz[row*XZW + DI + d];
        g_yg[row*DI + d] = (y + u * Dsk[d]) * siluf(z);
    }
}

// ---------------- head: out[b,t] = h . head_w + head_b, warp per row --------
__global__ void head_kernel(const float* __restrict__ hw,
                            const float* __restrict__ hb,
                            float* __restrict__ out) {
    int row  = blockIdx.x * (blockDim.x >> 5) + (threadIdx.x >> 5);
    int lane = threadIdx.x & 31;
    if (row >= BT) return;
    const float* p = g_h + (size_t)row * DM;
    float s = 0.f;
#pragma unroll
    for (int i = 0; i < 5; i++) {
        int c = lane + 32*i;
        s = fmaf(p[c], hw[c], s);
    }
#pragma unroll
    for (int o = 16; o; o >>= 1) s += __shfl_xor_sync(0xffffffffu, s, o);
    if (lane == 0) out[row] = s + hb[0];
}

// ---------------- orchestration ----------------
extern "C" void kernel_launch(void* const* d_in, const int* in_sizes, int n_in,
                              void* d_out, int out_size) {
    const float* x       = (const float*)d_in[0];
    const float* pre_w   = (const float*)d_in[1];
    const float* pre_b   = (const float*)d_in[2];
    const float* ln_g    = (const float*)d_in[3];
    const float* ln_b    = (const float*)d_in[4];
    const float* in_w    = (const float*)d_in[5];
    const float* conv_w  = (const float*)d_in[6];
    const float* conv_b  = (const float*)d_in[7];
    const float* xproj_w = (const float*)d_in[8];
    const float* dt_w    = (const float*)d_in[9];
    const float* dt_b    = (const float*)d_in[10];
    const float* A_log   = (const float*)d_in[11];
    const float* D_skip  = (const float*)d_in[12];
    const float* out_w   = (const float*)d_in[13];
    const float* head_w  = (const float*)d_in[14];
    const float* head_b  = (const float*)d_in[15];
    float* out = (float*)d_out;

    float *p_h, *p_ln, *p_xz, *p_u, *p_xdbl, *p_yg;
    cudaGetSymbolAddress((void**)&p_h,    g_h);
    cudaGetSymbolAddress((void**)&p_ln,   g_ln);
    cudaGetSymbolAddress((void**)&p_xz,   g_xz);
    cudaGetSymbolAddress((void**)&p_u,    g_u);
    cudaGetSymbolAddress((void**)&p_xdbl, g_xdbl);
    cudaGetSymbolAddress((void**)&p_yg,   g_yg);

    // stem
    stem_kernel<<<dim3(Tv, Bv), DM>>>(x, pre_w, pre_b);

    for (int i = 0; i < NB; i++) {
        // layernorm
        ln_kernel<<<BT/8, 256>>>(ln_g + i*DM, ln_b + i*DM);
        // in_proj: (BT,160) @ (640,160)^T -> g_xz
        sgemm_nt<false><<<dim3((XZW + 63)/64, BT/128), 256>>>(
            p_ln, in_w + (size_t)i*XZW*DM, nullptr, p_xz, BT, XZW, DM);
        // depthwise conv + silu
        conv_kernel<<<dim3(Tv/64, DI/64, Bv), 256>>>(
            conv_w + (size_t)i*DI*DC, conv_b + (size_t)i*DI);
        // x_proj: (BT,320) @ (138,320)^T -> g_xdbl
        sgemm_nt<false><<<dim3((XD + 63)/64, BT/128), 256>>>(
            p_u, xproj_w + (size_t)i*XD*DI, nullptr, p_xdbl, BT, XD, DI);
        // dt projection + softplus -> g_dd (b,d,t)
        dt_kernel<<<dim3(Tv/32, Bv), dim3(32, 8)>>>(
            dt_w + (size_t)i*DI*DTR, dt_b + (size_t)i*DI);
        // repack B,C
        bc_kernel<<<dim3(Tv/4, Bv), dim3(64, 4)>>>();
        // selective scan
        scan_kernel<<<(Bv*DI)/8, 256>>>(A_log + (size_t)i*DI*DS);
        // gate + transpose -> g_yg (b,t,d)
        gate_kernel<<<dim3(Tv/32, DI/32, Bv), dim3(32, 8)>>>(D_skip + (size_t)i*DI);
        // out_proj + residual: g_h += g_yg @ out_w^T
        sgemm_nt<true><<<dim3((DM + 63)/64, BT/128), 256>>>(
            p_yg, out_w + (size_t)i*DM*DI, p_h, p_h, BT, DM, DI);
    }

    // head
    head_kernel<<<BT/8, 256>>>(head_w, head_b, out);
}

// round 16
// speedup vs baseline: 1.2796x; 1.2771x over previous
#include <cuda_runtime.h>
#include <cuda_bf16.h>
#include <math.h>

// ---------------- problem constants ----------------
#define Bv   16
#define Tv   2048
#define DM   160        // d_model
#define DI   320        // d_inner
#define DS   64         // d_state
#define DTR  10         // dt_rank
#define CK   9          // stem conv kernel
#define DC   12         // mamba depthwise conv kernel
#define NB   8
#define BT   (Bv*Tv)    // 32768
#define XD   (DTR + 2*DS) // 138
#define XZW  (2*DI)     // 640

// ---------------- scratch (device globals, allocation-free) ----------------
__device__ float  g_h   [BT*DM];      // residual stream
__device__ float  g_ln  [BT*DM];      // layernorm output
__device__ float  g_xz  [BT*XZW];     // in_proj output (u | z)
__device__ float  g_u   [BT*DI];      // conv+silu output
__device__ float  g_xdbl[BT*XD];      // x_proj output
__device__ float2 g_dd  [Bv*DI*Tv];   // (delta, delta*u) in (b,d,t)
__device__ float2 g_bc  [BT*DS];      // (B_s, C_s) interleaved, (b,t,s)
__device__ float  g_ysc [Bv*DI*Tv];   // scan output in (b,d,t)
__device__ float  g_yg  [BT*DI];      // gated y in (b,t,d)

// ---------------- helpers ----------------
__device__ __forceinline__ float softplusf(float x) {
    return (x > 20.f) ? x : log1pf(expf(x));
}
__device__ __forceinline__ float siluf(float x) {
    return x / (1.f + expf(-x));
}
__device__ __forceinline__ unsigned f2tf32(float x) {
    unsigned r;
    asm("cvt.rna.tf32.f32 %0, %1;" : "=r"(r) : "f"(x));
    return r;
}
__device__ __forceinline__ void mma_tf32(float c[4],
                                         unsigned a0, unsigned a1, unsigned a2, unsigned a3,
                                         unsigned b0, unsigned b1) {
    asm volatile(
        "mma.sync.aligned.m16n8k8.row.col.f32.tf32.tf32.f32 "
        "{%0,%1,%2,%3}, {%4,%5,%6,%7}, {%8,%9}, {%0,%1,%2,%3};\n"
        : "+f"(c[0]), "+f"(c[1]), "+f"(c[2]), "+f"(c[3])
        : "r"(a0), "r"(a1), "r"(a2), "r"(a3), "r"(b0), "r"(b1));
}

// ---------------- stem: conv1d (K=9, same pad) + exact GELU ----------------
__global__ void stem_kernel(const float* __restrict__ x,
                            const float* __restrict__ pre_w,
                            const float* __restrict__ pre_b) {
    int t = blockIdx.x, b = blockIdx.y, c = threadIdx.x;
    __shared__ float xs[CK];
    if (c < CK) {
        int tt = t + c - CK/2;
        xs[c] = (tt >= 0 && tt < Tv) ? x[b*Tv + tt] : 0.f;
    }
    __syncthreads();
    float acc = pre_b[c];
#pragma unroll
    for (int k = 0; k < CK; k++) acc = fmaf(pre_w[c*CK + k], xs[k], acc);
    float g = 0.5f * acc * (1.f + erff(acc * 0.7071067811865475f));
    g_h[(b*Tv + t)*DM + c] = g;
}

// ---------------- LayerNorm over DM=160, one warp per row ----------------
__global__ void ln_kernel(const float* __restrict__ gamma,
                          const float* __restrict__ beta) {
    int row  = blockIdx.x * (blockDim.x >> 5) + (threadIdx.x >> 5);
    int lane = threadIdx.x & 31;
    if (row >= BT) return;
    const float* p = g_h + (size_t)row * DM;
    float v[5]; float s = 0.f;
#pragma unroll
    for (int i = 0; i < 5; i++) { v[i] = p[lane + 32*i]; s += v[i]; }
#pragma unroll
    for (int o = 16; o; o >>= 1) s += __shfl_xor_sync(0xffffffffu, s, o);
    float mean = s * (1.f / DM);
    float q = 0.f;
#pragma unroll
    for (int i = 0; i < 5; i++) { float d = v[i] - mean; q += d*d; }
#pragma unroll
    for (int o = 16; o; o >>= 1) q += __shfl_xor_sync(0xffffffffu, q, o);
    float r = rsqrtf(q * (1.f / DM) + 1e-5f);
    float* o = g_ln + (size_t)row * DM;
#pragma unroll
    for (int i = 0; i < 5; i++) {
        int c = lane + 32*i;
        o[c] = (v[i] - mean) * r * gamma[c] + beta[c];
    }
}

// ---------------- TF32 tensor-core GEMM: C[M,N] = A[M,K] @ W[N,K]^T (+Res) --
// BM=128, BN=64, BK=32, 256 threads, warp grid 4(m) x 2(n), warp tile 32x32.
// SMEM row stride 36 (== 4 mod 32) => all fragment loads conflict-free.
// Requires: M % 128 == 0, K % 32 == 0, N even. N guarded.
template <bool RES>
__global__ void __launch_bounds__(256)
tgemm_nt(const float* __restrict__ A, const float* __restrict__ W,
         const float* __restrict__ Res, float* __restrict__ C,
         int M, int N, int K) {
    __shared__ unsigned As[128][36];
    __shared__ unsigned Ws[64][36];

    const int tid  = threadIdx.x;
    const int wid  = tid >> 5;
    const int lane = tid & 31;
    const int wm   = wid & 3;          // 0..3 (m)
    const int wn   = wid >> 2;         // 0..1 (n)
    const int g    = lane >> 2;        // group id 0..7
    const int tg   = lane & 3;         // thread-in-group 0..3
    const int m0   = blockIdx.y * 128;
    const int n0   = blockIdx.x * 64;

    const int c4 = (tid & 7) * 4;      // k-offset of this thread's float4
    const int r0 = tid >> 3;           // 0..31 base row

    float acc[2][4][4];
#pragma unroll
    for (int mt = 0; mt < 2; mt++)
#pragma unroll
        for (int nt = 0; nt < 4; nt++)
#pragma unroll
            for (int i = 0; i < 4; i++) acc[mt][nt][i] = 0.f;

    for (int k0 = 0; k0 < K; k0 += 32) {
        // ---- load A tile 128x32 (4 float4 per thread) ----
#pragma unroll
        for (int p = 0; p < 4; p++) {
            int r = r0 + p * 32;
            float4 v = *reinterpret_cast<const float4*>(
                A + (size_t)(m0 + r) * K + k0 + c4);
            As[r][c4+0] = f2tf32(v.x);
            As[r][c4+1] = f2tf32(v.y);
            As[r][c4+2] = f2tf32(v.z);
            As[r][c4+3] = f2tf32(v.w);
        }
        // ---- load W tile 64x32 (2 float4 per thread, guarded) ----
#pragma unroll
        for (int p = 0; p < 2; p++) {
            int r = r0 + p * 32;
            float4 v = make_float4(0.f, 0.f, 0.f, 0.f);
            if (n0 + r < N)
                v = *reinterpret_cast<const float4*>(
                    W + (size_t)(n0 + r) * K + k0 + c4);
            Ws[r][c4+0] = f2tf32(v.x);
            Ws[r][c4+1] = f2tf32(v.y);
            Ws[r][c4+2] = f2tf32(v.z);
            Ws[r][c4+3] = f2tf32(v.w);
        }
        __syncthreads();

#pragma unroll
        for (int kk = 0; kk < 32; kk += 8) {
            unsigned af[2][4], bf[4][2];
#pragma unroll
            for (int mt = 0; mt < 2; mt++) {
                int row = wm * 32 + mt * 16;
                af[mt][0] = As[row + g    ][kk + tg    ];
                af[mt][1] = As[row + g + 8][kk + tg    ];
                af[mt][2] = As[row + g    ][kk + tg + 4];
                af[mt][3] = As[row + g + 8][kk + tg + 4];
            }
#pragma unroll
            for (int nt = 0; nt < 4; nt++) {
                int col = wn * 32 + nt * 8;
                bf[nt][0] = Ws[col + g][kk + tg    ];
                bf[nt][1] = Ws[col + g][kk + tg + 4];
            }
#pragma unroll
            for (int mt = 0; mt < 2; mt++)
#pragma unroll
                for (int nt = 0; nt < 4; nt++)
                    mma_tf32(acc[mt][nt],
                             af[mt][0], af[mt][1], af[mt][2], af[mt][3],
                             bf[nt][0], bf[nt][1]);
        }
        __syncthreads();
    }

    // ---- epilogue ----
#pragma unroll
    for (int mt = 0; mt < 2; mt++) {
        int row = m0 + wm * 32 + mt * 16 + g;
#pragma unroll
        for (int nt = 0; nt < 4; nt++) {
            int col = n0 + wn * 32 + nt * 8 + tg * 2;
            if (col < N) {   // N even, col even => col+1 also valid
                size_t o0 = (size_t)row * N + col;
                size_t o1 = (size_t)(row + 8) * N + col;
                float2 v0 = make_float2(acc[mt][nt][0], acc[mt][nt][1]);
                float2 v1 = make_float2(acc[mt][nt][2], acc[mt][nt][3]);
                if (RES) {
                    float2 r0v = *reinterpret_cast<const float2*>(Res + o0);
                    float2 r1v = *reinterpret_cast<const float2*>(Res + o1);
                    v0.x += r0v.x; v0.y += r0v.y;
                    v1.x += r1v.x; v1.y += r1v.y;
                }
                *reinterpret_cast<float2*>(C + o0) = v0;
                *reinterpret_cast<float2*>(C + o1) = v1;
            }
        }
    }
}

// ---------------- depthwise causal conv (K=12) + bias + SiLU ----------------
__global__ void __launch_bounds__(256)
conv_kernel(const float* __restrict__ cw, const float* __restrict__ cb) {
    __shared__ float uin[64 + DC - 1][64];   // [75][64]
    __shared__ float cwT[DC][64];
    __shared__ float cbs[64];
    int t0 = blockIdx.x * 64;
    int d0 = blockIdx.y * 64;
    int b  = blockIdx.z;
    int tid = threadIdx.x;

    for (int idx = tid; idx < (64 + DC - 1) * 64; idx += 256) {
        int r = idx >> 6, dd = idx & 63;
        int t = t0 - (DC - 1) + r;
        uin[r][dd] = (t >= 0) ? g_xz[((size_t)(b*Tv) + t)*XZW + d0 + dd] : 0.f;
    }
    for (int idx = tid; idx < 64 * DC; idx += 256) {
        int dd = idx / DC, k = idx % DC;
        cwT[k][dd] = cw[(d0 + dd)*DC + k];
    }
    if (tid < 64) cbs[tid] = cb[d0 + tid];
    __syncthreads();

    for (int q = 0; q < 16; q++) {
        int lin = tid + q * 256;
        int tt = lin >> 6, dd = lin & 63;
        float acc = cbs[dd];
#pragma unroll
        for (int k = 0; k < DC; k++) acc = fmaf(uin[tt + k][dd], cwT[k][dd], acc);
        g_u[((size_t)(b*Tv) + t0 + tt)*DI + d0 + dd] = siluf(acc);
    }
}

// ---------------- dt projection + softplus, write (delta, delta*u) ----------
__global__ void __launch_bounds__(256)
dt_kernel(const float* __restrict__ dtw, const float* __restrict__ dtb) {
    __shared__ float xdt[32][11];        // [t][r] padded
    __shared__ float dtws[DI*DTR];       // 3200 floats
    __shared__ float us[32][33];         // [t][d_local]
    int t0 = blockIdx.x * 32;
    int b  = blockIdx.y;
    int tx = threadIdx.x, ty = threadIdx.y;
    int tid = ty * 32 + tx;

    for (int idx = tid; idx < 32 * DTR; idx += 256)
        xdt[idx / DTR][idx % DTR] = g_xdbl[((size_t)(b*Tv) + t0 + idx/DTR)*XD + idx%DTR];
    for (int idx = tid; idx < DI*DTR; idx += 256) dtws[idx] = dtw[idx];
    __syncthreads();

    for (int dch = 0; dch < DI/32; dch++) {
        for (int p = 0; p < 4; p++) {
            int lin = tid + p * 256;
            int tl = lin >> 5, dl = lin & 31;
            us[tl][dl] = g_u[((size_t)(b*Tv) + t0 + tl)*DI + dch*32 + dl];
        }
        __syncthreads();
#pragma unroll
        for (int jj = 0; jj < 4; jj++) {
            int dl = ty * 4 + jj;
            int d  = dch * 32 + dl;
            float acc = dtb[d];
#pragma unroll
            for (int r = 0; r < DTR; r++)
                acc = fmaf(xdt[tx][r], dtws[d*DTR + r], acc);
            float delta = softplusf(acc);
            float uu = us[tx][dl];
            g_dd[((size_t)(b*DI + d))*Tv + t0 + tx] = make_float2(delta, delta * uu);
        }
        __syncthreads();
    }
}

// ---------------- repack B,C columns of x_dbl into interleaved float2 -------
__global__ void bc_kernel() {
    int s = threadIdx.x;                     // 0..63
    int t = blockIdx.x * blockDim.y + threadIdx.y;
    int b = blockIdx.y;
    size_t row = (size_t)b*Tv + t;
    float Bs = g_xdbl[row*XD + DTR + s];
    float Cs = g_xdbl[row*XD + DTR + DS + s];
    g_bc[row*DS + s] = make_float2(Bs, Cs);
}

// ---------------- selective scan: one warp per (b,d) channel ----------------
__global__ void __launch_bounds__(256)
scan_kernel(const float* __restrict__ A_log) {
    int w    = blockIdx.x * 8 + (threadIdx.x >> 5);
    int lane = threadIdx.x & 31;
    int b = w / DI, d = w % DI;

    float2 al = reinterpret_cast<const float2*>(A_log + (size_t)d*DS)[lane];
    const float L2E = 1.4426950408889634f;
    float a0 = -expf(al.x) * L2E;
    float a1 = -expf(al.y) * L2E;

    const float2* ddp = g_dd + (size_t)(b*DI + d)*Tv;
    const float2* bcp = g_bc + (size_t)b*Tv*DS + 2*lane;
    float*        yo  = g_ysc + (size_t)(b*DI + d)*Tv;

    float h0 = 0.f, h1 = 0.f, ys = 0.f;
    for (int t = 0; t < Tv; t += 32) {
#pragma unroll
        for (int j = 0; j < 32; j++) {
            float2 dv  = ddp[t + j];
            float4 bcv = *reinterpret_cast<const float4*>(bcp + (size_t)(t + j)*DS);
            float dA0 = exp2f(dv.x * a0);
            float dA1 = exp2f(dv.x * a1);
            h0 = fmaf(h0, dA0, dv.y * bcv.x);
            h1 = fmaf(h1, dA1, dv.y * bcv.z);
            float p = fmaf(h0, bcv.y, h1 * bcv.w);
#pragma unroll
            for (int o = 16; o; o >>= 1) p += __shfl_xor_sync(0xffffffffu, p, o);
            if (lane == j) ys = p;
        }
        yo[t + lane] = ys;
    }
}

// ---------------- gate: yg(b,t,d) = (ysc + u*Dskip) * silu(z), transpose -----
__global__ void __launch_bounds__(256)
gate_kernel(const float* __restrict__ Dsk) {
    __shared__ float ts[32][33];
    int t0 = blockIdx.x * 32;
    int d0 = blockIdx.y * 32;
    int b  = blockIdx.z;
    int tx = threadIdx.x, ty = threadIdx.y;

#pragma unroll
    for (int p = 0; p < 4; p++) {
        int r = ty + p * 8;
        ts[r][tx] = g_ysc[((size_t)(b*DI) + d0 + r)*Tv + t0 + tx];
    }
    __syncthreads();
#pragma unroll
    for (int p = 0; p < 4; p++) {
        int tt = ty + p * 8;
        int d  = d0 + tx;
        size_t row = (size_t)b*Tv + t0 + tt;
        float y = ts[tx][tt];
        float u = g_u[row*DI + d];
        float z = g_xz[row*XZW + DI + d];
        g_yg[row*DI + d] = (y + u * Dsk[d]) * siluf(z);
    }
}

// ---------------- head: out[b,t] = h . head_w + head_b, warp per row --------
__global__ void head_kernel(const float* __restrict__ hw,
                            const float* __restrict__ hb,
                            float* __restrict__ out) {
    int row  = blockIdx.x * (blockDim.x >> 5) + (threadIdx.x >> 5);
    int lane = threadIdx.x & 31;
    if (row >= BT) return;
    const float* p = g_h + (size_t)row * DM;
    float s = 0.f;
#pragma unroll
    for (int i = 0; i < 5; i++) {
        int c = lane + 32*i;
        s = fmaf(p[c], hw[c], s);
    }
#pragma unroll
    for (int o = 16; o; o >>= 1) s += __shfl_xor_sync(0xffffffffu, s, o);
    if (lane == 0) out[row] = s + hb[0];
}

// ---------------- orchestration ----------------
extern "C" void kernel_launch(void* const* d_in, const int* in_sizes, int n_in,
                              void* d_out, int out_size) {
    const float* x       = (const float*)d_in[0];
    const float* pre_w   = (const float*)d_in[1];
    const float* pre_b   = (const float*)d_in[2];
    const float* ln_g    = (const float*)d_in[3];
    const float* ln_b    = (const float*)d_in[4];
    const float* in_w    = (const float*)d_in[5];
    const float* conv_w  = (const float*)d_in[6];
    const float* conv_b  = (const float*)d_in[7];
    const float* xproj_w = (const float*)d_in[8];
    const float* dt_w    = (const float*)d_in[9];
    const float* dt_b    = (const float*)d_in[10];
    const float* A_log   = (const float*)d_in[11];
    const float* D_skip  = (const float*)d_in[12];
    const float* out_w   = (const float*)d_in[13];
    const float* head_w  = (const float*)d_in[14];
    const float* head_b  = (const float*)d_in[15];
    float* out = (float*)d_out;

    float *p_h, *p_ln, *p_xz, *p_u, *p_xdbl, *p_yg;
    cudaGetSymbolAddress((void**)&p_h,    g_h);
    cudaGetSymbolAddress((void**)&p_ln,   g_ln);
    cudaGetSymbolAddress((void**)&p_xz,   g_xz);
    cudaGetSymbolAddress((void**)&p_u,    g_u);
    cudaGetSymbolAddress((void**)&p_xdbl, g_xdbl);
    cudaGetSymbolAddress((void**)&p_yg,   g_yg);

    // stem
    stem_kernel<<<dim3(Tv, Bv), DM>>>(x, pre_w, pre_b);

    for (int i = 0; i < NB; i++) {
        // layernorm
        ln_kernel<<<BT/8, 256>>>(ln_g + i*DM, ln_b + i*DM);
        // in_proj: (BT,160) @ (640,160)^T -> g_xz   [tensor cores]
        tgemm_nt<false><<<dim3((XZW + 63)/64, BT/128), 256>>>(
            p_ln, in_w + (size_t)i*XZW*DM, nullptr, p_xz, BT, XZW, DM);
        // depthwise conv + silu
        conv_kernel<<<dim3(Tv/64, DI/64, Bv), 256>>>(
            conv_w + (size_t)i*DI*DC, conv_b + (size_t)i*DI);
        // x_proj: (BT,320) @ (138,320)^T -> g_xdbl  [tensor cores]
        tgemm_nt<false><<<dim3((XD + 63)/64, BT/128), 256>>>(
            p_u, xproj_w + (size_t)i*XD*DI, nullptr, p_xdbl, BT, XD, DI);
        // dt projection + softplus -> g_dd (b,d,t)
        dt_kernel<<<dim3(Tv/32, Bv), dim3(32, 8)>>>(
            dt_w + (size_t)i*DI*DTR, dt_b + (size_t)i*DI);
        // repack B,C
        bc_kernel<<<dim3(Tv/4, Bv), dim3(64, 4)>>>();
        // selective scan
        scan_kernel<<<(Bv*DI)/8, 256>>>(A_log + (size_t)i*DI*DS);
        // gate + transpose -> g_yg (b,t,d)
        gate_kernel<<<dim3(Tv/32, DI/32, Bv), dim3(32, 8)>>>(D_skip + (size_t)i*DI);
        // out_proj + residual: g_h += g_yg @ out_w^T  [tensor cores]
        tgemm_nt<true><<<dim3((DM + 63)/64, BT/128), 256>>>(
            p_yg, out_w + (size_t)i*DM*DI, p_h, p_h, BT, DM, DI);
    }

    // head
    head_kernel<<<BT/8, 256>>>(head_w, head_b, out);
}

// round 17
// speedup vs baseline: 1.3362x; 1.0442x over previous
#include <cuda_runtime.h>
#include <cuda_bf16.h>
#include <math.h>

// ---------------- problem constants ----------------
#define Bv   16
#define Tv   2048
#define DM   160        // d_model
#define DI   320        // d_inner
#define DS   64         // d_state
#define DTR  10         // dt_rank
#define CK   9          // stem conv kernel
#define DC   12         // mamba depthwise conv kernel
#define NB   8
#define BT   (Bv*Tv)    // 32768
#define XD   (DTR + 2*DS) // 138
#define XZW  (2*DI)     // 640

// ---------------- scratch (device globals, allocation-free) ----------------
__device__ float  g_h   [BT*DM];      // residual stream
__device__ float  g_ln  [BT*DM];      // layernorm output
__device__ float  g_xz  [BT*XZW];     // in_proj output (u | z)
__device__ float  g_u   [BT*DI];      // conv+silu output
__device__ float  g_xdbl[BT*XD];      // x_proj output
__device__ float2 g_dd  [Bv*DI*Tv];   // (delta, delta*u) in (b,d,t)
__device__ float2 g_bc  [BT*DS];      // (B_s, C_s) interleaved, (b,t,s)
__device__ float  g_ysc [Bv*DI*Tv];   // scan output in (b,d,t)
__device__ float  g_yg  [BT*DI];      // gated y in (b,t,d)

// ---------------- helpers ----------------
__device__ __forceinline__ float softplusf(float x) {
    return (x > 20.f) ? x : log1pf(expf(x));
}
__device__ __forceinline__ float siluf(float x) {
    return x / (1.f + expf(-x));
}
__device__ __forceinline__ unsigned f2tf32(float x) {
    unsigned r;
    asm("cvt.rna.tf32.f32 %0, %1;" : "=r"(r) : "f"(x));
    return r;
}
__device__ __forceinline__ void mma_tf32(float c[4],
                                         unsigned a0, unsigned a1, unsigned a2, unsigned a3,
                                         unsigned b0, unsigned b1) {
    asm volatile(
        "mma.sync.aligned.m16n8k8.row.col.f32.tf32.tf32.f32 "
        "{%0,%1,%2,%3}, {%4,%5,%6,%7}, {%8,%9}, {%0,%1,%2,%3};\n"
        : "+f"(c[0]), "+f"(c[1]), "+f"(c[2]), "+f"(c[3])
        : "r"(a0), "r"(a1), "r"(a2), "r"(a3), "r"(b0), "r"(b1));
}

// ---------------- stem: conv1d (K=9, same pad) + exact GELU ----------------
__global__ void stem_kernel(const float* __restrict__ x,
                            const float* __restrict__ pre_w,
                            const float* __restrict__ pre_b) {
    int t = blockIdx.x, b = blockIdx.y, c = threadIdx.x;
    __shared__ float xs[CK];
    if (c < CK) {
        int tt = t + c - CK/2;
        xs[c] = (tt >= 0 && tt < Tv) ? x[b*Tv + tt] : 0.f;
    }
    __syncthreads();
    float acc = pre_b[c];
#pragma unroll
    for (int k = 0; k < CK; k++) acc = fmaf(pre_w[c*CK + k], xs[k], acc);
    float g = 0.5f * acc * (1.f + erff(acc * 0.7071067811865475f));
    g_h[(b*Tv + t)*DM + c] = g;
}

// ---------------- LayerNorm over DM=160, one warp per row ----------------
__global__ void ln_kernel(const float* __restrict__ gamma,
                          const float* __restrict__ beta) {
    int row  = blockIdx.x * (blockDim.x >> 5) + (threadIdx.x >> 5);
    int lane = threadIdx.x & 31;
    if (row >= BT) return;
    const float* p = g_h + (size_t)row * DM;
    float v[5]; float s = 0.f;
#pragma unroll
    for (int i = 0; i < 5; i++) { v[i] = p[lane + 32*i]; s += v[i]; }
#pragma unroll
    for (int o = 16; o; o >>= 1) s += __shfl_xor_sync(0xffffffffu, s, o);
    float mean = s * (1.f / DM);
    float q = 0.f;
#pragma unroll
    for (int i = 0; i < 5; i++) { float d = v[i] - mean; q += d*d; }
#pragma unroll
    for (int o = 16; o; o >>= 1) q += __shfl_xor_sync(0xffffffffu, q, o);
    float r = rsqrtf(q * (1.f / DM) + 1e-5f);
    float* o = g_ln + (size_t)row * DM;
#pragma unroll
    for (int i = 0; i < 5; i++) {
        int c = lane + 32*i;
        o[c] = (v[i] - mean) * r * gamma[c] + beta[c];
    }
}

// ---------------- TF32 tensor-core GEMM: C[M,N] = A[M,K] @ W[N,K]^T (+Res) --
// BM=128, BN=64, BK=32, 256 threads, warp grid 4(m) x 2(n), warp tile 32x32.
// SMEM row stride 36 (== 4 mod 32) => all fragment loads conflict-free.
// Requires: M % 128 == 0, K % 32 == 0, N even. N guarded.
template <bool RES>
__global__ void __launch_bounds__(256)
tgemm_nt(const float* __restrict__ A, const float* __restrict__ W,
         const float* __restrict__ Res, float* __restrict__ C,
         int M, int N, int K) {
    __shared__ unsigned As[128][36];
    __shared__ unsigned Ws[64][36];

    const int tid  = threadIdx.x;
    const int wid  = tid >> 5;
    const int lane = tid & 31;
    const int wm   = wid & 3;          // 0..3 (m)
    const int wn   = wid >> 2;         // 0..1 (n)
    const int g    = lane >> 2;        // group id 0..7
    const int tg   = lane & 3;         // thread-in-group 0..3
    const int m0   = blockIdx.y * 128;
    const int n0   = blockIdx.x * 64;

    const int c4 = (tid & 7) * 4;      // k-offset of this thread's float4
    const int r0 = tid >> 3;           // 0..31 base row

    float acc[2][4][4];
#pragma unroll
    for (int mt = 0; mt < 2; mt++)
#pragma unroll
        for (int nt = 0; nt < 4; nt++)
#pragma unroll
            for (int i = 0; i < 4; i++) acc[mt][nt][i] = 0.f;

    for (int k0 = 0; k0 < K; k0 += 32) {
        // ---- load A tile 128x32 (4 float4 per thread) ----
#pragma unroll
        for (int p = 0; p < 4; p++) {
            int r = r0 + p * 32;
            float4 v = *reinterpret_cast<const float4*>(
                A + (size_t)(m0 + r) * K + k0 + c4);
            As[r][c4+0] = f2tf32(v.x);
            As[r][c4+1] = f2tf32(v.y);
            As[r][c4+2] = f2tf32(v.z);
            As[r][c4+3] = f2tf32(v.w);
        }
        // ---- load W tile 64x32 (2 float4 per thread, guarded) ----
#pragma unroll
        for (int p = 0; p < 2; p++) {
            int r = r0 + p * 32;
            float4 v = make_float4(0.f, 0.f, 0.f, 0.f);
            if (n0 + r < N)
                v = *reinterpret_cast<const float4*>(
                    W + (size_t)(n0 + r) * K + k0 + c4);
            Ws[r][c4+0] = f2tf32(v.x);
            Ws[r][c4+1] = f2tf32(v.y);
            Ws[r][c4+2] = f2tf32(v.z);
            Ws[r][c4+3] = f2tf32(v.w);
        }
        __syncthreads();

#pragma unroll
        for (int kk = 0; kk < 32; kk += 8) {
            unsigned af[2][4], bf[4][2];
#pragma unroll
            for (int mt = 0; mt < 2; mt++) {
                int row = wm * 32 + mt * 16;
                af[mt][0] = As[row + g    ][kk + tg    ];
                af[mt][1] = As[row + g + 8][kk + tg    ];
                af[mt][2] = As[row + g    ][kk + tg + 4];
                af[mt][3] = As[row + g + 8][kk + tg + 4];
            }
#pragma unroll
            for (int nt = 0; nt < 4; nt++) {
                int col = wn * 32 + nt * 8;
                bf[nt][0] = Ws[col + g][kk + tg    ];
                bf[nt][1] = Ws[col + g][kk + tg + 4];
            }
#pragma unroll
            for (int mt = 0; mt < 2; mt++)
#pragma unroll
                for (int nt = 0; nt < 4; nt++)
                    mma_tf32(acc[mt][nt],
                             af[mt][0], af[mt][1], af[mt][2], af[mt][3],
                             bf[nt][0], bf[nt][1]);
        }
        __syncthreads();
    }

    // ---- epilogue ----
#pragma unroll
    for (int mt = 0; mt < 2; mt++) {
        int row = m0 + wm * 32 + mt * 16 + g;
#pragma unroll
        for (int nt = 0; nt < 4; nt++) {
            int col = n0 + wn * 32 + nt * 8 + tg * 2;
            if (col < N) {   // N even, col even => col+1 also valid
                size_t o0 = (size_t)row * N + col;
                size_t o1 = (size_t)(row + 8) * N + col;
                float2 v0 = make_float2(acc[mt][nt][0], acc[mt][nt][1]);
                float2 v1 = make_float2(acc[mt][nt][2], acc[mt][nt][3]);
                if (RES) {
                    float2 r0v = *reinterpret_cast<const float2*>(Res + o0);
                    float2 r1v = *reinterpret_cast<const float2*>(Res + o1);
                    v0.x += r0v.x; v0.y += r0v.y;
                    v1.x += r1v.x; v1.y += r1v.y;
                }
                *reinterpret_cast<float2*>(C + o0) = v0;
                *reinterpret_cast<float2*>(C + o1) = v1;
            }
        }
    }
}

// ---------------- depthwise causal conv (K=12) + bias + SiLU ----------------
__global__ void __launch_bounds__(256)
conv_kernel(const float* __restrict__ cw, const float* __restrict__ cb) {
    __shared__ float uin[64 + DC - 1][64];   // [75][64]
    __shared__ float cwT[DC][64];
    __shared__ float cbs[64];
    int t0 = blockIdx.x * 64;
    int d0 = blockIdx.y * 64;
    int b  = blockIdx.z;
    int tid = threadIdx.x;

    for (int idx = tid; idx < (64 + DC - 1) * 64; idx += 256) {
        int r = idx >> 6, dd = idx & 63;
        int t = t0 - (DC - 1) + r;
        uin[r][dd] = (t >= 0) ? g_xz[((size_t)(b*Tv) + t)*XZW + d0 + dd] : 0.f;
    }
    for (int idx = tid; idx < 64 * DC; idx += 256) {
        int dd = idx / DC, k = idx % DC;
        cwT[k][dd] = cw[(d0 + dd)*DC + k];
    }
    if (tid < 64) cbs[tid] = cb[d0 + tid];
    __syncthreads();

    for (int q = 0; q < 16; q++) {
        int lin = tid + q * 256;
        int tt = lin >> 6, dd = lin & 63;
        float acc = cbs[dd];
#pragma unroll
        for (int k = 0; k < DC; k++) acc = fmaf(uin[tt + k][dd], cwT[k][dd], acc);
        g_u[((size_t)(b*Tv) + t0 + tt)*DI + d0 + dd] = siluf(acc);
    }
}

// ---------------- dt projection + softplus, write (delta, delta*u) ----------
__global__ void __launch_bounds__(256)
dt_kernel(const float* __restrict__ dtw, const float* __restrict__ dtb) {
    __shared__ float xdt[32][11];        // [t][r] padded
    __shared__ float dtws[DI*DTR];       // 3200 floats
    __shared__ float us[32][33];         // [t][d_local]
    int t0 = blockIdx.x * 32;
    int b  = blockIdx.y;
    int tx = threadIdx.x, ty = threadIdx.y;
    int tid = ty * 32 + tx;

    for (int idx = tid; idx < 32 * DTR; idx += 256)
        xdt[idx / DTR][idx % DTR] = g_xdbl[((size_t)(b*Tv) + t0 + idx/DTR)*XD + idx%DTR];
    for (int idx = tid; idx < DI*DTR; idx += 256) dtws[idx] = dtw[idx];
    __syncthreads();

    for (int dch = 0; dch < DI/32; dch++) {
        for (int p = 0; p < 4; p++) {
            int lin = tid + p * 256;
            int tl = lin >> 5, dl = lin & 31;
            us[tl][dl] = g_u[((size_t)(b*Tv) + t0 + tl)*DI + dch*32 + dl];
        }
        __syncthreads();
#pragma unroll
        for (int jj = 0; jj < 4; jj++) {
            int dl = ty * 4 + jj;
            int d  = dch * 32 + dl;
            float acc = dtb[d];
#pragma unroll
            for (int r = 0; r < DTR; r++)
                acc = fmaf(xdt[tx][r], dtws[d*DTR + r], acc);
            float delta = softplusf(acc);
            float uu = us[tx][dl];
            g_dd[((size_t)(b*DI + d))*Tv + t0 + tx] = make_float2(delta, delta * uu);
        }
        __syncthreads();
    }
}

// ---------------- repack B,C columns of x_dbl into interleaved float2 -------
__global__ void bc_kernel() {
    int s = threadIdx.x;                     // 0..63
    int t = blockIdx.x * blockDim.y + threadIdx.y;
    int b = blockIdx.y;
    size_t row = (size_t)b*Tv + t;
    float Bs = g_xdbl[row*XD + DTR + s];
    float Cs = g_xdbl[row*XD + DTR + DS + s];
    g_bc[row*DS + s] = make_float2(Bs, Cs);
}

// ---------------- selective scan: one warp per (b,d) channel ----------------
__global__ void __launch_bounds__(256)
scan_kernel(const float* __restrict__ A_log) {
    int w    = blockIdx.x * 8 + (threadIdx.x >> 5);
    int lane = threadIdx.x & 31;
    int b = w / DI, d = w % DI;

    float2 al = reinterpret_cast<const float2*>(A_log + (size_t)d*DS)[lane];
    const float L2E = 1.4426950408889634f;
    float a0 = -expf(al.x) * L2E;
    float a1 = -expf(al.y) * L2E;

    const float2* ddp = g_dd + (size_t)(b*DI + d)*Tv;
    const float2* bcp = g_bc + (size_t)b*Tv*DS + 2*lane;
    float*        yo  = g_ysc + (size_t)(b*DI + d)*Tv;

    float h0 = 0.f, h1 = 0.f, ys = 0.f;
    for (int t = 0; t < Tv; t += 32) {
#pragma unroll
        for (int j = 0; j < 32; j++) {
            float2 dv  = ddp[t + j];
            float4 bcv = *reinterpret_cast<const float4*>(bcp + (size_t)(t + j)*DS);
            float dA0 = exp2f(dv.x * a0);
            float dA1 = exp2f(dv.x * a1);
            h0 = fmaf(h0, dA0, dv.y * bcv.x);
            h1 = fmaf(h1, dA1, dv.y * bcv.z);
            float p = fmaf(h0, bcv.y, h1 * bcv.w);
#pragma unroll
            for (int o = 16; o; o >>= 1) p += __shfl_xor_sync(0xffffffffu, p, o);
            if (lane == j) ys = p;
        }
        yo[t + lane] = ys;
    }
}

// ---------------- gate: yg(b,t,d) = (ysc + u*Dskip) * silu(z), transpose -----
__global__ void __launch_bounds__(256)
gate_kernel(const float* __restrict__ Dsk) {
    __shared__ float ts[32][33];
    int t0 = blockIdx.x * 32;
    int d0 = blockIdx.y * 32;
    int b  = blockIdx.z;
    int tx = threadIdx.x, ty = threadIdx.y;

#pragma unroll
    for (int p = 0; p < 4; p++) {
        int r = ty + p * 8;
        ts[r][tx] = g_ysc[((size_t)(b*DI) + d0 + r)*Tv + t0 + tx];
    }
    __syncthreads();
#pragma unroll
    for (int p = 0; p < 4; p++) {
        int tt = ty + p * 8;
        int d  = d0 + tx;
        size_t row = (size_t)b*Tv + t0 + tt;
        float y = ts[tx][tt];
        float u = g_u[row*DI + d];
        float z = g_xz[row*XZW + DI + d];
        g_yg[row*DI + d] = (y + u * Dsk[d]) * siluf(z);
    }
}

// ---------------- head: out[b,t] = h . head_w + head_b, warp per row --------
__global__ void head_kernel(const float* __restrict__ hw,
                            const float* __restrict__ hb,
                            float* __restrict__ out) {
    int row  = blockIdx.x * (blockDim.x >> 5) + (threadIdx.x >> 5);
    int lane = threadIdx.x & 31;
    if (row >= BT) return;
    const float* p = g_h + (size_t)row * DM;
    float s = 0.f;
#pragma unroll
    for (int i = 0; i < 5; i++) {
        int c = lane + 32*i;
        s = fmaf(p[c], hw[c], s);
    }
#pragma unroll
    for (int o = 16; o; o >>= 1) s += __shfl_xor_sync(0xffffffffu, s, o);
    if (lane == 0) out[row] = s + hb[0];
}

// ---------------- orchestration ----------------
extern "C" void kernel_launch(void* const* d_in, const int* in_sizes, int n_in,
                              void* d_out, int out_size) {
    const float* x       = (const float*)d_in[0];
    const float* pre_w   = (const float*)d_in[1];
    const float* pre_b   = (const float*)d_in[2];
    const float* ln_g    = (const float*)d_in[3];
    const float* ln_b    = (const float*)d_in[4];
    const float* in_w    = (const float*)d_in[5];
    const float* conv_w  = (const float*)d_in[6];
    const float* conv_b  = (const float*)d_in[7];
    const float* xproj_w = (const float*)d_in[8];
    const float* dt_w    = (const float*)d_in[9];
    const float* dt_b    = (const float*)d_in[10];
    const float* A_log   = (const float*)d_in[11];
    const float* D_skip  = (const float*)d_in[12];
    const float* out_w   = (const float*)d_in[13];
    const float* head_w  = (const float*)d_in[14];
    const float* head_b  = (const float*)d_in[15];
    float* out = (float*)d_out;

    float *p_h, *p_ln, *p_xz, *p_u, *p_xdbl, *p_yg;
    cudaGetSymbolAddress((void**)&p_h,    g_h);
    cudaGetSymbolAddress((void**)&p_ln,   g_ln);
    cudaGetSymbolAddress((void**)&p_xz,   g_xz);
    cudaGetSymbolAddress((void**)&p_u,    g_u);
    cudaGetSymbolAddress((void**)&p_xdbl, g_xdbl);
    cudaGetSymbolAddress((void**)&p_yg,   g_yg);

    // stem
    stem_kernel<<<dim3(Tv, Bv), DM>>>(x, pre_w, pre_b);

    for (int i = 0; i < NB; i++) {
        // layernorm
        ln_kernel<<<BT/8, 256>>>(ln_g + i*DM, ln_b + i*DM);
        // in_proj: (BT,160) @ (640,160)^T -> g_xz   [tensor cores]
        tgemm_nt<false><<<dim3((XZW + 63)/64, BT/128), 256>>>(
            p_ln, in_w + (size_t)i*XZW*DM, nullptr, p_xz, BT, XZW, DM);
        // depthwise conv + silu
        conv_kernel<<<dim3(Tv/64, DI/64, Bv), 256>>>(
            conv_w + (size_t)i*DI*DC, conv_b + (size_t)i*DI);
        // x_proj: (BT,320) @ (138,320)^T -> g_xdbl  [tensor cores]
        tgemm_nt<false><<<dim3((XD + 63)/64, BT/128), 256>>>(
            p_u, xproj_w + (size_t)i*XD*DI, nullptr, p_xdbl, BT, XD, DI);
        // dt projection + softplus -> g_dd (b,d,t)
        dt_kernel<<<dim3(Tv/32, Bv), dim3(32, 8)>>>(
            dt_w + (size_t)i*DI*DTR, dt_b + (size_t)i*DI);
        // repack B,C
        bc_kernel<<<dim3(Tv/4, Bv), dim3(64, 4)>>>();
        // selective scan
        scan_kernel<<<(Bv*DI)/8, 256>>>(A_log + (size_t)i*DI*DS);
        // gate + transpose -> g_yg (b,t,d)
        gate_kernel<<<dim3(Tv/32, DI/32, Bv), dim3(32, 8)>>>(D_skip + (size_t)i*DI);
        // out_proj + residual: g_h += g_yg @ out_w^T  [tensor cores]
        tgemm_nt<true><<<dim3((DM + 63)/64, BT/128), 256>>>(
            p_yg, out_w + (size_t)i*DM*DI, p_h, p_h, BT, DM, DI);
    }

    // head
    head_kernel<<<BT/8, 256>>>(head_w, head_b, out);
}